// round 11
// baseline (speedup 1.0000x reference)
#include <cuda_runtime.h>
#include <cuda_fp16.h>
#include <cstdint>

// ============================================================================
// NSFPRawMLP: x[262144,3] -> 128 -> (7x 128x128 + ReLU) -> 3
// R11: ALL 7 weight layers resident in SMEM (224KB), 1 CTA/SM, 256 thr/CTA.
// ONE barrier after the initial cp.async burst; the 7-layer mainloop runs with
// ZERO synchronization -- warps free-run and de-phase, covering each other's
// epilogue/prologue bubbles. pp-outer overlapped epilogue + f16x2 epilogue,
// single-product fp16 MMA, 32 rows/warp.
// ============================================================================

#define NROWS   262144
#define NHID    7
#define ROWS_PER_CTA 256
#define NTILES  (NROWS / ROWS_PER_CTA)   // 1024 CTAs
#define THREADS 256                      // 8 warps, 32 rows/warp

// Weight images: [layer][32768 B] fp16.
// byte = n*256 + ((chunk ^ (n&7))<<4) + (k&7)*2, chunk = k>>3  (XOR swizzle)
static __device__ __align__(128) unsigned char g_wimg[NHID][32768];

// ---------------------------------------------------------------------------
// SMEM layout: 7 weight buffers + f16x2 biases. W0/b0/Wout/bout read from gmem.
// ---------------------------------------------------------------------------
#define SM_WBUF    0                     // 7 x 32768 = 229376
#define SM_BIASH   229376                // 7*64 half2 = 1792
#define SMEM_SZ    231168                // 225.75 KB <= 227 KB/block

// ---------------------------------------------------------------------------
// PTX helpers (base-target, sm_80+)
// ---------------------------------------------------------------------------
__device__ __forceinline__ uint32_t smem_u32(const void* p) {
    uint32_t a;
    asm("{ .reg .u64 t; cvta.to.shared.u64 t, %1; cvt.u32.u64 %0, t; }"
        : "=r"(a) : "l"(p));
    return a;
}

#define CP_ASYNC16(dst_u32, src_ptr) \
    asm volatile("cp.async.cg.shared.global [%0], [%1], 16;" \
                 :: "r"(dst_u32), "l"(src_ptr) : "memory")
#define CP_COMMIT() asm volatile("cp.async.commit_group;" ::: "memory")
#define CP_WAIT(n)  asm volatile("cp.async.wait_group %0;" :: "n"(n) : "memory")

#define LDSM4(r0, r1, r2, r3, addr) \
    asm volatile("ldmatrix.sync.aligned.m8n8.x4.shared.b16 {%0,%1,%2,%3}, [%4];" \
                 : "=r"(r0), "=r"(r1), "=r"(r2), "=r"(r3) : "r"(addr))

#define MMA16816(C, A, b0_, b1_) \
    asm volatile("mma.sync.aligned.m16n8k16.row.col.f32.f16.f16.f32 " \
                 "{%0,%1,%2,%3},{%4,%5,%6,%7},{%8,%9},{%0,%1,%2,%3};" \
                 : "+f"((C)[0]), "+f"((C)[1]), "+f"((C)[2]), "+f"((C)[3]) \
                 : "r"((A)[0]), "r"((A)[1]), "r"((A)[2]), "r"((A)[3]), \
                   "r"(b0_), "r"(b1_))

// pack two fp32 -> fp16x2 (round-to-nearest)
__device__ __forceinline__ uint32_t pack_f16(float v0, float v1) {
    uint32_t r;
    asm("cvt.rn.f16x2.f32 %0, %1, %2;" : "=r"(r) : "f"(v1), "f"(v0));
    return r;
}

__device__ __forceinline__ float relu(float v) { return fmaxf(v, 0.0f); }

// f16x2 epilogue op: pack(c0,c1) + bias2 (f16), relu via hmax2
__device__ __forceinline__ uint32_t epi_op(float c0, float c1, uint32_t b2) {
    uint32_t v = pack_f16(c0, c1);
    __half2 hv = __hadd2(*reinterpret_cast<__half2*>(&v),
                         *reinterpret_cast<const __half2*>(&b2));
    const __half2 z = __floats2half2_rn(0.f, 0.f);
    hv = __hmax2(hv, z);
    return *reinterpret_cast<uint32_t*>(&hv);
}

__device__ __forceinline__ void epi_sg(uint32_t (&Aout)[4],
                                       const float (&C0)[4], const float (&C1)[4],
                                       uint32_t b20, uint32_t b21) {
    Aout[0] = epi_op(C0[0], C0[1], b20);
    Aout[1] = epi_op(C0[2], C0[3], b20);
    Aout[2] = epi_op(C1[0], C1[1], b21);
    Aout[3] = epi_op(C1[2], C1[3], b21);
}

// ---------------------------------------------------------------------------
// Prep kernel: Wh fp32 -> fp16 swizzled image.
// ---------------------------------------------------------------------------
__global__ void prep_weights_kernel(const float* __restrict__ Wh) {
    int idx = blockIdx.x * blockDim.x + threadIdx.x;
    if (idx >= NHID * 128 * 128) return;
    int l = idx >> 14;
    int n = (idx >> 7) & 127;
    int k = idx & 127;
    __half w = __float2half_rn(Wh[idx]);
    uint32_t chunk = (uint32_t)k >> 3;
    uint32_t off = (uint32_t)n * 256 + ((chunk ^ ((uint32_t)n & 7)) << 4)
                 + ((uint32_t)k & 7) * 2;
    *(__half*)&g_wimg[l][off] = w;
}

// ---------------------------------------------------------------------------
// One hidden layer: pp-outer k-loop, per-block epilogue overlapped. No syncs.
// ---------------------------------------------------------------------------
__device__ __forceinline__ void hidden_layer(
    uint32_t wb, const uint32_t (&swz)[8], int q,
    uint32_t (&Aia)[8][4], uint32_t (&Aib)[8][4],
    uint32_t (&Aoa)[8][4], uint32_t (&Aob)[8][4],
    const uint32_t* __restrict__ b2) {
    float Ca[16][4], Cb[16][4];
    uint32_t h[2][8];
    LDSM4(h[0][0], h[0][1], h[0][2], h[0][3], wb + swz[0]);
    LDSM4(h[0][4], h[0][5], h[0][6], h[0][7], wb + swz[0] + 4096);
    #pragma unroll
    for (int grp = 0; grp < 32; grp++) {
        const int cur = grp & 1, nxt = cur ^ 1;
        const int pp = grp >> 3, s = grp & 7;
        if (grp + 1 < 32) {
            const int pp1 = (grp + 1) >> 3, s1 = (grp + 1) & 7;
            const uint32_t a0 = wb + swz[s1] + (uint32_t)(2 * pp1) * 4096;
            LDSM4(h[nxt][0], h[nxt][1], h[nxt][2], h[nxt][3], a0);
            LDSM4(h[nxt][4], h[nxt][5], h[nxt][6], h[nxt][7], a0 + 4096);
        }
        if (s == 0) {
            #pragma unroll
            for (int j = 0; j < 4; j++) {
                Ca[4 * pp + j][0] = 0.f; Ca[4 * pp + j][1] = 0.f;
                Ca[4 * pp + j][2] = 0.f; Ca[4 * pp + j][3] = 0.f;
                Cb[4 * pp + j][0] = 0.f; Cb[4 * pp + j][1] = 0.f;
                Cb[4 * pp + j][2] = 0.f; Cb[4 * pp + j][3] = 0.f;
            }
        }
        MMA16816(Ca[4 * pp + 0], Aia[s], h[cur][0], h[cur][1]);
        MMA16816(Cb[4 * pp + 0], Aib[s], h[cur][0], h[cur][1]);
        MMA16816(Ca[4 * pp + 1], Aia[s], h[cur][2], h[cur][3]);
        MMA16816(Cb[4 * pp + 1], Aib[s], h[cur][2], h[cur][3]);
        MMA16816(Ca[4 * pp + 2], Aia[s], h[cur][4], h[cur][5]);
        MMA16816(Cb[4 * pp + 2], Aib[s], h[cur][4], h[cur][5]);
        MMA16816(Ca[4 * pp + 3], Aia[s], h[cur][6], h[cur][7]);
        MMA16816(Cb[4 * pp + 3], Aib[s], h[cur][6], h[cur][7]);
        if (s == 1 && pp > 0) {
            const int p0 = pp - 1;
            #pragma unroll
            for (int e = 0; e < 2; e++) {
                const int sg = 2 * p0 + e;
                const uint32_t b20 = b2[8 * sg + q];
                const uint32_t b21 = b2[8 * sg + 4 + q];
                epi_sg(Aoa[sg], Ca[2 * sg], Ca[2 * sg + 1], b20, b21);
                epi_sg(Aob[sg], Cb[2 * sg], Cb[2 * sg + 1], b20, b21);
            }
        }
    }
    #pragma unroll
    for (int e = 0; e < 2; e++) {
        const int sg = 6 + e;
        const uint32_t b20 = b2[8 * sg + q];
        const uint32_t b21 = b2[8 * sg + 4 + q];
        epi_sg(Aoa[sg], Ca[2 * sg], Ca[2 * sg + 1], b20, b21);
        epi_sg(Aob[sg], Cb[2 * sg], Cb[2 * sg + 1], b20, b21);
    }
}

// ---------------------------------------------------------------------------
// Final layer: per-block fp32 bias+relu+[128->3] projection (params via gmem).
// ---------------------------------------------------------------------------
__device__ __forceinline__ void final_layer(
    uint32_t wb, const uint32_t (&swz)[8], int q,
    uint32_t (&Aia)[8][4], uint32_t (&Aib)[8][4],
    const float* __restrict__ bl, const float* __restrict__ wout,
    float (&o)[12]) {
    float Ca[16][4], Cb[16][4];
    uint32_t h[2][8];
    LDSM4(h[0][0], h[0][1], h[0][2], h[0][3], wb + swz[0]);
    LDSM4(h[0][4], h[0][5], h[0][6], h[0][7], wb + swz[0] + 4096);
    #pragma unroll
    for (int grp = 0; grp < 32; grp++) {
        const int cur = grp & 1, nxt = cur ^ 1;
        const int pp = grp >> 3, s = grp & 7;
        if (grp + 1 < 32) {
            const int pp1 = (grp + 1) >> 3, s1 = (grp + 1) & 7;
            const uint32_t a0 = wb + swz[s1] + (uint32_t)(2 * pp1) * 4096;
            LDSM4(h[nxt][0], h[nxt][1], h[nxt][2], h[nxt][3], a0);
            LDSM4(h[nxt][4], h[nxt][5], h[nxt][6], h[nxt][7], a0 + 4096);
        }
        if (s == 0) {
            #pragma unroll
            for (int j = 0; j < 4; j++) {
                Ca[4 * pp + j][0] = 0.f; Ca[4 * pp + j][1] = 0.f;
                Ca[4 * pp + j][2] = 0.f; Ca[4 * pp + j][3] = 0.f;
                Cb[4 * pp + j][0] = 0.f; Cb[4 * pp + j][1] = 0.f;
                Cb[4 * pp + j][2] = 0.f; Cb[4 * pp + j][3] = 0.f;
            }
        }
        MMA16816(Ca[4 * pp + 0], Aia[s], h[cur][0], h[cur][1]);
        MMA16816(Cb[4 * pp + 0], Aib[s], h[cur][0], h[cur][1]);
        MMA16816(Ca[4 * pp + 1], Aia[s], h[cur][2], h[cur][3]);
        MMA16816(Cb[4 * pp + 1], Aib[s], h[cur][2], h[cur][3]);
        MMA16816(Ca[4 * pp + 2], Aia[s], h[cur][4], h[cur][5]);
        MMA16816(Cb[4 * pp + 2], Aib[s], h[cur][4], h[cur][5]);
        MMA16816(Ca[4 * pp + 3], Aia[s], h[cur][6], h[cur][7]);
        MMA16816(Cb[4 * pp + 3], Aib[s], h[cur][6], h[cur][7]);
        if (s == 1 && pp > 0) {
            const int p0 = pp - 1;
            #pragma unroll
            for (int g = 4 * p0; g < 4 * p0 + 4; g++) {
                const int c = 8 * g + 2 * q;
                const float2 bb  = *(const float2*)&bl[c];
                const float2 wj0 = *(const float2*)&wout[0 * 128 + c];
                const float2 wj1 = *(const float2*)&wout[1 * 128 + c];
                const float2 wj2 = *(const float2*)&wout[2 * 128 + c];
                float v00 = relu(Ca[g][0] + bb.x), v01 = relu(Ca[g][1] + bb.y);
                float v10 = relu(Ca[g][2] + bb.x), v11 = relu(Ca[g][3] + bb.y);
                float v20 = relu(Cb[g][0] + bb.x), v21 = relu(Cb[g][1] + bb.y);
                float v30 = relu(Cb[g][2] + bb.x), v31 = relu(Cb[g][3] + bb.y);
                o[0]  = fmaf(v00, wj0.x, fmaf(v01, wj0.y, o[0]));
                o[1]  = fmaf(v00, wj1.x, fmaf(v01, wj1.y, o[1]));
                o[2]  = fmaf(v00, wj2.x, fmaf(v01, wj2.y, o[2]));
                o[3]  = fmaf(v10, wj0.x, fmaf(v11, wj0.y, o[3]));
                o[4]  = fmaf(v10, wj1.x, fmaf(v11, wj1.y, o[4]));
                o[5]  = fmaf(v10, wj2.x, fmaf(v11, wj2.y, o[5]));
                o[6]  = fmaf(v20, wj0.x, fmaf(v21, wj0.y, o[6]));
                o[7]  = fmaf(v20, wj1.x, fmaf(v21, wj1.y, o[7]));
                o[8]  = fmaf(v20, wj2.x, fmaf(v21, wj2.y, o[8]));
                o[9]  = fmaf(v30, wj0.x, fmaf(v31, wj0.y, o[9]));
                o[10] = fmaf(v30, wj1.x, fmaf(v31, wj1.y, o[10]));
                o[11] = fmaf(v30, wj2.x, fmaf(v31, wj2.y, o[11]));
            }
        }
    }
    #pragma unroll
    for (int g = 12; g < 16; g++) {
        const int c = 8 * g + 2 * q;
        const float2 bb  = *(const float2*)&bl[c];
        const float2 wj0 = *(const float2*)&wout[0 * 128 + c];
        const float2 wj1 = *(const float2*)&wout[1 * 128 + c];
        const float2 wj2 = *(const float2*)&wout[2 * 128 + c];
        float v00 = relu(Ca[g][0] + bb.x), v01 = relu(Ca[g][1] + bb.y);
        float v10 = relu(Ca[g][2] + bb.x), v11 = relu(Ca[g][3] + bb.y);
        float v20 = relu(Cb[g][0] + bb.x), v21 = relu(Cb[g][1] + bb.y);
        float v30 = relu(Cb[g][2] + bb.x), v31 = relu(Cb[g][3] + bb.y);
        o[0]  = fmaf(v00, wj0.x, fmaf(v01, wj0.y, o[0]));
        o[1]  = fmaf(v00, wj1.x, fmaf(v01, wj1.y, o[1]));
        o[2]  = fmaf(v00, wj2.x, fmaf(v01, wj2.y, o[2]));
        o[3]  = fmaf(v10, wj0.x, fmaf(v11, wj0.y, o[3]));
        o[4]  = fmaf(v10, wj1.x, fmaf(v11, wj1.y, o[4]));
        o[5]  = fmaf(v10, wj2.x, fmaf(v11, wj2.y, o[5]));
        o[6]  = fmaf(v20, wj0.x, fmaf(v21, wj0.y, o[6]));
        o[7]  = fmaf(v20, wj1.x, fmaf(v21, wj1.y, o[7]));
        o[8]  = fmaf(v20, wj2.x, fmaf(v21, wj2.y, o[8]));
        o[9]  = fmaf(v30, wj0.x, fmaf(v31, wj0.y, o[9]));
        o[10] = fmaf(v30, wj1.x, fmaf(v31, wj1.y, o[10]));
        o[11] = fmaf(v30, wj2.x, fmaf(v31, wj2.y, o[11]));
    }
}

// ---------------------------------------------------------------------------
// Main kernel: 256 rows per CTA, 8 warps (32 rows each), 1 CTA per SM.
// ---------------------------------------------------------------------------
__global__ void __launch_bounds__(THREADS, 1)
mlp_kernel(const float* __restrict__ x,
           const float* __restrict__ W0,
           const float* __restrict__ b0,
           const float* __restrict__ bh,
           const float* __restrict__ Wout,
           const float* __restrict__ bout,
           float* __restrict__ out) {
    extern __shared__ char smem[];
    const uint32_t sb = smem_u32(smem);
    const int tid  = threadIdx.x;
    const int wid  = tid >> 5;
    const int lane = tid & 31;
    const int q    = lane & 3;

    // ---- prefetch ALL 7 layer images (7 groups, 8 x 16B per thread each) ----
    #pragma unroll
    for (int l = 0; l < NHID; l++) {
        const char* src = (const char*)&g_wimg[l][0];
        uint32_t dst = sb + SM_WBUF + (uint32_t)l * 32768;
        #pragma unroll
        for (int i = 0; i < 8; i++)
            CP_ASYNC16(dst + (uint32_t)(tid + i * THREADS) * 16,
                       src + (size_t)(tid + i * THREADS) * 16);
        CP_COMMIT();
    }

    // ---- stage f16x2 biases ----
    {
        uint32_t* b2s = (uint32_t*)(smem + SM_BIASH);
        for (int i = tid; i < NHID * 64; i += THREADS)
            b2s[i] = pack_f16(bh[2 * i], bh[2 * i + 1]);
    }

    const int rbase = blockIdx.x * ROWS_PER_CTA + wid * 32 + (lane >> 2);
    const int g0 = rbase, g1 = rbase + 8, g2 = rbase + 16, g3 = rbase + 24;

    // ---- layer 0: [3 -> 128] fp32 FFMA (W0/b0 from gmem) -> fp16 A frags ----
    uint32_t A0a[8][4], A0b[8][4], A1a[8][4], A1b[8][4];
    {
        const float x00 = x[g0 * 3 + 0], x01 = x[g0 * 3 + 1], x02 = x[g0 * 3 + 2];
        const float x10 = x[g1 * 3 + 0], x11 = x[g1 * 3 + 1], x12 = x[g1 * 3 + 2];
        const float x20 = x[g2 * 3 + 0], x21 = x[g2 * 3 + 1], x22 = x[g2 * 3 + 2];
        const float x30 = x[g3 * 3 + 0], x31 = x[g3 * 3 + 1], x32 = x[g3 * 3 + 2];
        #pragma unroll
        for (int s = 0; s < 8; s++) {
            const int c0 = 16 * s + 2 * q;
            #pragma unroll
            for (int h = 0; h < 2; h++) {
                const int ca = c0 + 8 * h;
                const float wa0 = W0[ca * 3 + 0], wa1 = W0[ca * 3 + 1], wa2 = W0[ca * 3 + 2];
                const float wb0 = W0[(ca + 1) * 3 + 0], wb1 = W0[(ca + 1) * 3 + 1], wb2 = W0[(ca + 1) * 3 + 2];
                const float ba = b0[ca], bb = b0[ca + 1];
                float v00 = relu(fmaf(x00, wa0, fmaf(x01, wa1, fmaf(x02, wa2, ba))));
                float v01 = relu(fmaf(x00, wb0, fmaf(x01, wb1, fmaf(x02, wb2, bb))));
                float v10 = relu(fmaf(x10, wa0, fmaf(x11, wa1, fmaf(x12, wa2, ba))));
                float v11 = relu(fmaf(x10, wb0, fmaf(x11, wb1, fmaf(x12, wb2, bb))));
                A0a[s][2 * h + 0] = pack_f16(v00, v01);
                A0a[s][2 * h + 1] = pack_f16(v10, v11);
                float v20 = relu(fmaf(x20, wa0, fmaf(x21, wa1, fmaf(x22, wa2, ba))));
                float v21 = relu(fmaf(x20, wb0, fmaf(x21, wb1, fmaf(x22, wb2, bb))));
                float v30 = relu(fmaf(x30, wa0, fmaf(x31, wa1, fmaf(x32, wa2, ba))));
                float v31 = relu(fmaf(x30, wb0, fmaf(x31, wb1, fmaf(x32, wb2, bb))));
                A0b[s][2 * h + 0] = pack_f16(v20, v21);
                A0b[s][2 * h + 1] = pack_f16(v30, v31);
            }
        }
    }

    // per-thread ldmatrix address pieces
    const uint32_t nloc = (uint32_t)((lane & 7) + ((lane >> 4) & 1) * 8);
    const uint32_t jbit = (uint32_t)((lane >> 3) & 1);
    uint32_t swz[8];
    #pragma unroll
    for (int s = 0; s < 8; s++)
        swz[s] = nloc * 256 + ((((uint32_t)(2 * s) + jbit) ^ (nloc & 7)) << 4);

    const uint32_t* b2base = (const uint32_t*)(smem + SM_BIASH);

    // ---- THE ONLY BARRIER: all weights + biases resident and visible ----
    CP_WAIT(0);
    __syncthreads();

    // ---- 6 hidden layers, zero synchronization ----
    #pragma unroll 1
    for (int it = 0; it < 3; it++) {
        const int l0 = 2 * it;
        hidden_layer(sb + SM_WBUF + (uint32_t)l0 * 32768, swz, q,
                     A0a, A0b, A1a, A1b, b2base + l0 * 64);
        hidden_layer(sb + SM_WBUF + (uint32_t)(l0 + 1) * 32768, swz, q,
                     A1a, A1b, A0a, A0b, b2base + (l0 + 1) * 64);
    }

    // ---- final layer (l=6): MMA + fused [128->3] projection ----
    float o[12];
    #pragma unroll
    for (int i = 0; i < 12; i++) o[i] = 0.f;
    final_layer(sb + SM_WBUF + 6u * 32768, swz, q, A0a, A0b,
                bh + 6 * 128, Wout, o);

    #pragma unroll
    for (int d = 1; d <= 2; d <<= 1) {
        #pragma unroll
        for (int i = 0; i < 12; i++)
            o[i] += __shfl_xor_sync(0xFFFFFFFF, o[i], d);
    }
    if (q == 0) {
        const float bo0 = bout[0], bo1 = bout[1], bo2 = bout[2];
        out[g0 * 3 + 0] = o[0] + bo0;
        out[g0 * 3 + 1] = o[1] + bo1;
        out[g0 * 3 + 2] = o[2] + bo2;
        out[g1 * 3 + 0] = o[3] + bo0;
        out[g1 * 3 + 1] = o[4] + bo1;
        out[g1 * 3 + 2] = o[5] + bo2;
        out[g2 * 3 + 0] = o[6] + bo0;
        out[g2 * 3 + 1] = o[7] + bo1;
        out[g2 * 3 + 2] = o[8] + bo2;
        out[g3 * 3 + 0] = o[9] + bo0;
        out[g3 * 3 + 1] = o[10] + bo1;
        out[g3 * 3 + 2] = o[11] + bo2;
    }
}

// ---------------------------------------------------------------------------
// kernel_launch
// ---------------------------------------------------------------------------
extern "C" void kernel_launch(void* const* d_in, const int* in_sizes, int n_in,
                              void* d_out, int out_size) {
    const float* x    = (const float*)d_in[0];   // [262144,3]
    const float* W0   = (const float*)d_in[1];   // [128,3]
    const float* b0   = (const float*)d_in[2];   // [128]
    const float* Wh   = (const float*)d_in[3];   // [7,128,128]
    const float* bh   = (const float*)d_in[4];   // [7,128]
    const float* Wout = (const float*)d_in[5];   // [3,128]
    const float* bout = (const float*)d_in[6];   // [3]
    float* out = (float*)d_out;                  // [262144,3]

    static bool attr_set = false;
    if (!attr_set) {
        cudaFuncSetAttribute(mlp_kernel,
                             cudaFuncAttributeMaxDynamicSharedMemorySize, SMEM_SZ);
        attr_set = true;
    }

    prep_weights_kernel<<<(NHID * 128 * 128 + 255) / 256, 256>>>(Wh);
    mlp_kernel<<<NTILES, THREADS, SMEM_SZ>>>(x, W0, b0, bh, Wout, bout, out);
}

// round 12
// speedup vs baseline: 1.0201x; 1.0201x over previous
#include <cuda_runtime.h>
#include <cuda_fp16.h>
#include <cstdint>

// ============================================================================
// NSFPRawMLP: x[262144,3] -> 128 -> (7x 128x128 + ReLU) -> 3
// R12: PERSISTENT CTAs. grid=148 (1 CTA/SM), each CTA loads all 7 weight
// images into SMEM once (one barrier, ever), then loops over ~7 row-tiles of
// 256 rows with ZERO synchronization and ZERO weight reloads. Warps free-run
// and de-phase across the whole kernel. pp-outer overlapped f16x2 epilogue,
// single-product fp16 MMA, 32 rows/warp.
// ============================================================================

#define NROWS    262144
#define NHID     7
#define TILE_ROWS 256
#define NTILES   (NROWS / TILE_ROWS)     // 1024 tiles
#define NCTAS    148                     // persistent: one per SM
#define THREADS  256                     // 8 warps, 32 rows/warp

// Weight images: [layer][32768 B] fp16.
// byte = n*256 + ((chunk ^ (n&7))<<4) + (k&7)*2, chunk = k>>3  (XOR swizzle)
static __device__ __align__(128) unsigned char g_wimg[NHID][32768];

// ---------------------------------------------------------------------------
// SMEM layout: 7 weight buffers + f16x2 biases. W0/b0/Wout/bout via gmem/L2.
// ---------------------------------------------------------------------------
#define SM_WBUF    0                     // 7 x 32768 = 229376
#define SM_BIASH   229376                // 7*64 half2 = 1792
#define SMEM_SZ    231168                // 225.75 KB

// ---------------------------------------------------------------------------
// PTX helpers (base-target, sm_80+)
// ---------------------------------------------------------------------------
__device__ __forceinline__ uint32_t smem_u32(const void* p) {
    uint32_t a;
    asm("{ .reg .u64 t; cvta.to.shared.u64 t, %1; cvt.u32.u64 %0, t; }"
        : "=r"(a) : "l"(p));
    return a;
}

#define CP_ASYNC16(dst_u32, src_ptr) \
    asm volatile("cp.async.cg.shared.global [%0], [%1], 16;" \
                 :: "r"(dst_u32), "l"(src_ptr) : "memory")
#define CP_COMMIT() asm volatile("cp.async.commit_group;" ::: "memory")
#define CP_WAIT(n)  asm volatile("cp.async.wait_group %0;" :: "n"(n) : "memory")

#define LDSM4(r0, r1, r2, r3, addr) \
    asm volatile("ldmatrix.sync.aligned.m8n8.x4.shared.b16 {%0,%1,%2,%3}, [%4];" \
                 : "=r"(r0), "=r"(r1), "=r"(r2), "=r"(r3) : "r"(addr))

#define MMA16816(C, A, b0_, b1_) \
    asm volatile("mma.sync.aligned.m16n8k16.row.col.f32.f16.f16.f32 " \
                 "{%0,%1,%2,%3},{%4,%5,%6,%7},{%8,%9},{%0,%1,%2,%3};" \
                 : "+f"((C)[0]), "+f"((C)[1]), "+f"((C)[2]), "+f"((C)[3]) \
                 : "r"((A)[0]), "r"((A)[1]), "r"((A)[2]), "r"((A)[3]), \
                   "r"(b0_), "r"(b1_))

// pack two fp32 -> fp16x2 (round-to-nearest)
__device__ __forceinline__ uint32_t pack_f16(float v0, float v1) {
    uint32_t r;
    asm("cvt.rn.f16x2.f32 %0, %1, %2;" : "=r"(r) : "f"(v1), "f"(v0));
    return r;
}

__device__ __forceinline__ float relu(float v) { return fmaxf(v, 0.0f); }

// f16x2 epilogue op: pack(c0,c1) + bias2 (f16), relu via hmax2
__device__ __forceinline__ uint32_t epi_op(float c0, float c1, uint32_t b2) {
    uint32_t v = pack_f16(c0, c1);
    __half2 hv = __hadd2(*reinterpret_cast<__half2*>(&v),
                         *reinterpret_cast<const __half2*>(&b2));
    const __half2 z = __floats2half2_rn(0.f, 0.f);
    hv = __hmax2(hv, z);
    return *reinterpret_cast<uint32_t*>(&hv);
}

__device__ __forceinline__ void epi_sg(uint32_t (&Aout)[4],
                                       const float (&C0)[4], const float (&C1)[4],
                                       uint32_t b20, uint32_t b21) {
    Aout[0] = epi_op(C0[0], C0[1], b20);
    Aout[1] = epi_op(C0[2], C0[3], b20);
    Aout[2] = epi_op(C1[0], C1[1], b21);
    Aout[3] = epi_op(C1[2], C1[3], b21);
}

// ---------------------------------------------------------------------------
// Prep kernel: Wh fp32 -> fp16 swizzled image.
// ---------------------------------------------------------------------------
__global__ void prep_weights_kernel(const float* __restrict__ Wh) {
    int idx = blockIdx.x * blockDim.x + threadIdx.x;
    if (idx >= NHID * 128 * 128) return;
    int l = idx >> 14;
    int n = (idx >> 7) & 127;
    int k = idx & 127;
    __half w = __float2half_rn(Wh[idx]);
    uint32_t chunk = (uint32_t)k >> 3;
    uint32_t off = (uint32_t)n * 256 + ((chunk ^ ((uint32_t)n & 7)) << 4)
                 + ((uint32_t)k & 7) * 2;
    *(__half*)&g_wimg[l][off] = w;
}

// ---------------------------------------------------------------------------
// One hidden layer: pp-outer k-loop, per-block epilogue overlapped. No syncs.
// ---------------------------------------------------------------------------
__device__ __forceinline__ void hidden_layer(
    uint32_t wb, const uint32_t (&swz)[8], int q,
    uint32_t (&Aia)[8][4], uint32_t (&Aib)[8][4],
    uint32_t (&Aoa)[8][4], uint32_t (&Aob)[8][4],
    const uint32_t* __restrict__ b2) {
    float Ca[16][4], Cb[16][4];
    uint32_t h[2][8];
    LDSM4(h[0][0], h[0][1], h[0][2], h[0][3], wb + swz[0]);
    LDSM4(h[0][4], h[0][5], h[0][6], h[0][7], wb + swz[0] + 4096);
    #pragma unroll
    for (int grp = 0; grp < 32; grp++) {
        const int cur = grp & 1, nxt = cur ^ 1;
        const int pp = grp >> 3, s = grp & 7;
        if (grp + 1 < 32) {
            const int pp1 = (grp + 1) >> 3, s1 = (grp + 1) & 7;
            const uint32_t a0 = wb + swz[s1] + (uint32_t)(2 * pp1) * 4096;
            LDSM4(h[nxt][0], h[nxt][1], h[nxt][2], h[nxt][3], a0);
            LDSM4(h[nxt][4], h[nxt][5], h[nxt][6], h[nxt][7], a0 + 4096);
        }
        if (s == 0) {
            #pragma unroll
            for (int j = 0; j < 4; j++) {
                Ca[4 * pp + j][0] = 0.f; Ca[4 * pp + j][1] = 0.f;
                Ca[4 * pp + j][2] = 0.f; Ca[4 * pp + j][3] = 0.f;
                Cb[4 * pp + j][0] = 0.f; Cb[4 * pp + j][1] = 0.f;
                Cb[4 * pp + j][2] = 0.f; Cb[4 * pp + j][3] = 0.f;
            }
        }
        MMA16816(Ca[4 * pp + 0], Aia[s], h[cur][0], h[cur][1]);
        MMA16816(Cb[4 * pp + 0], Aib[s], h[cur][0], h[cur][1]);
        MMA16816(Ca[4 * pp + 1], Aia[s], h[cur][2], h[cur][3]);
        MMA16816(Cb[4 * pp + 1], Aib[s], h[cur][2], h[cur][3]);
        MMA16816(Ca[4 * pp + 2], Aia[s], h[cur][4], h[cur][5]);
        MMA16816(Cb[4 * pp + 2], Aib[s], h[cur][4], h[cur][5]);
        MMA16816(Ca[4 * pp + 3], Aia[s], h[cur][6], h[cur][7]);
        MMA16816(Cb[4 * pp + 3], Aib[s], h[cur][6], h[cur][7]);
        if (s == 1 && pp > 0) {
            const int p0 = pp - 1;
            #pragma unroll
            for (int e = 0; e < 2; e++) {
                const int sg = 2 * p0 + e;
                const uint32_t b20 = b2[8 * sg + q];
                const uint32_t b21 = b2[8 * sg + 4 + q];
                epi_sg(Aoa[sg], Ca[2 * sg], Ca[2 * sg + 1], b20, b21);
                epi_sg(Aob[sg], Cb[2 * sg], Cb[2 * sg + 1], b20, b21);
            }
        }
    }
    #pragma unroll
    for (int e = 0; e < 2; e++) {
        const int sg = 6 + e;
        const uint32_t b20 = b2[8 * sg + q];
        const uint32_t b21 = b2[8 * sg + 4 + q];
        epi_sg(Aoa[sg], Ca[2 * sg], Ca[2 * sg + 1], b20, b21);
        epi_sg(Aob[sg], Cb[2 * sg], Cb[2 * sg + 1], b20, b21);
    }
}

// ---------------------------------------------------------------------------
// Final layer: per-block fp32 bias+relu+[128->3] projection (params via L2).
// ---------------------------------------------------------------------------
__device__ __forceinline__ void final_layer(
    uint32_t wb, const uint32_t (&swz)[8], int q,
    uint32_t (&Aia)[8][4], uint32_t (&Aib)[8][4],
    const float* __restrict__ bl, const float* __restrict__ wout,
    float (&o)[12]) {
    float Ca[16][4], Cb[16][4];
    uint32_t h[2][8];
    LDSM4(h[0][0], h[0][1], h[0][2], h[0][3], wb + swz[0]);
    LDSM4(h[0][4], h[0][5], h[0][6], h[0][7], wb + swz[0] + 4096);
    #pragma unroll
    for (int grp = 0; grp < 32; grp++) {
        const int cur = grp & 1, nxt = cur ^ 1;
        const int pp = grp >> 3, s = grp & 7;
        if (grp + 1 < 32) {
            const int pp1 = (grp + 1) >> 3, s1 = (grp + 1) & 7;
            const uint32_t a0 = wb + swz[s1] + (uint32_t)(2 * pp1) * 4096;
            LDSM4(h[nxt][0], h[nxt][1], h[nxt][2], h[nxt][3], a0);
            LDSM4(h[nxt][4], h[nxt][5], h[nxt][6], h[nxt][7], a0 + 4096);
        }
        if (s == 0) {
            #pragma unroll
            for (int j = 0; j < 4; j++) {
                Ca[4 * pp + j][0] = 0.f; Ca[4 * pp + j][1] = 0.f;
                Ca[4 * pp + j][2] = 0.f; Ca[4 * pp + j][3] = 0.f;
                Cb[4 * pp + j][0] = 0.f; Cb[4 * pp + j][1] = 0.f;
                Cb[4 * pp + j][2] = 0.f; Cb[4 * pp + j][3] = 0.f;
            }
        }
        MMA16816(Ca[4 * pp + 0], Aia[s], h[cur][0], h[cur][1]);
        MMA16816(Cb[4 * pp + 0], Aib[s], h[cur][0], h[cur][1]);
        MMA16816(Ca[4 * pp + 1], Aia[s], h[cur][2], h[cur][3]);
        MMA16816(Cb[4 * pp + 1], Aib[s], h[cur][2], h[cur][3]);
        MMA16816(Ca[4 * pp + 2], Aia[s], h[cur][4], h[cur][5]);
        MMA16816(Cb[4 * pp + 2], Aib[s], h[cur][4], h[cur][5]);
        MMA16816(Ca[4 * pp + 3], Aia[s], h[cur][6], h[cur][7]);
        MMA16816(Cb[4 * pp + 3], Aib[s], h[cur][6], h[cur][7]);
        if (s == 1 && pp > 0) {
            const int p0 = pp - 1;
            #pragma unroll
            for (int g = 4 * p0; g < 4 * p0 + 4; g++) {
                const int c = 8 * g + 2 * q;
                const float2 bb  = *(const float2*)&bl[c];
                const float2 wj0 = *(const float2*)&wout[0 * 128 + c];
                const float2 wj1 = *(const float2*)&wout[1 * 128 + c];
                const float2 wj2 = *(const float2*)&wout[2 * 128 + c];
                float v00 = relu(Ca[g][0] + bb.x), v01 = relu(Ca[g][1] + bb.y);
                float v10 = relu(Ca[g][2] + bb.x), v11 = relu(Ca[g][3] + bb.y);
                float v20 = relu(Cb[g][0] + bb.x), v21 = relu(Cb[g][1] + bb.y);
                float v30 = relu(Cb[g][2] + bb.x), v31 = relu(Cb[g][3] + bb.y);
                o[0]  = fmaf(v00, wj0.x, fmaf(v01, wj0.y, o[0]));
                o[1]  = fmaf(v00, wj1.x, fmaf(v01, wj1.y, o[1]));
                o[2]  = fmaf(v00, wj2.x, fmaf(v01, wj2.y, o[2]));
                o[3]  = fmaf(v10, wj0.x, fmaf(v11, wj0.y, o[3]));
                o[4]  = fmaf(v10, wj1.x, fmaf(v11, wj1.y, o[4]));
                o[5]  = fmaf(v10, wj2.x, fmaf(v11, wj2.y, o[5]));
                o[6]  = fmaf(v20, wj0.x, fmaf(v21, wj0.y, o[6]));
                o[7]  = fmaf(v20, wj1.x, fmaf(v21, wj1.y, o[7]));
                o[8]  = fmaf(v20, wj2.x, fmaf(v21, wj2.y, o[8]));
                o[9]  = fmaf(v30, wj0.x, fmaf(v31, wj0.y, o[9]));
                o[10] = fmaf(v30, wj1.x, fmaf(v31, wj1.y, o[10]));
                o[11] = fmaf(v30, wj2.x, fmaf(v31, wj2.y, o[11]));
            }
        }
    }
    #pragma unroll
    for (int g = 12; g < 16; g++) {
        const int c = 8 * g + 2 * q;
        const float2 bb  = *(const float2*)&bl[c];
        const float2 wj0 = *(const float2*)&wout[0 * 128 + c];
        const float2 wj1 = *(const float2*)&wout[1 * 128 + c];
        const float2 wj2 = *(const float2*)&wout[2 * 128 + c];
        float v00 = relu(Ca[g][0] + bb.x), v01 = relu(Ca[g][1] + bb.y);
        float v10 = relu(Ca[g][2] + bb.x), v11 = relu(Ca[g][3] + bb.y);
        float v20 = relu(Cb[g][0] + bb.x), v21 = relu(Cb[g][1] + bb.y);
        float v30 = relu(Cb[g][2] + bb.x), v31 = relu(Cb[g][3] + bb.y);
        o[0]  = fmaf(v00, wj0.x, fmaf(v01, wj0.y, o[0]));
        o[1]  = fmaf(v00, wj1.x, fmaf(v01, wj1.y, o[1]));
        o[2]  = fmaf(v00, wj2.x, fmaf(v01, wj2.y, o[2]));
        o[3]  = fmaf(v10, wj0.x, fmaf(v11, wj0.y, o[3]));
        o[4]  = fmaf(v10, wj1.x, fmaf(v11, wj1.y, o[4]));
        o[5]  = fmaf(v10, wj2.x, fmaf(v11, wj2.y, o[5]));
        o[6]  = fmaf(v20, wj0.x, fmaf(v21, wj0.y, o[6]));
        o[7]  = fmaf(v20, wj1.x, fmaf(v21, wj1.y, o[7]));
        o[8]  = fmaf(v20, wj2.x, fmaf(v21, wj2.y, o[8]));
        o[9]  = fmaf(v30, wj0.x, fmaf(v31, wj0.y, o[9]));
        o[10] = fmaf(v30, wj1.x, fmaf(v31, wj1.y, o[10]));
        o[11] = fmaf(v30, wj2.x, fmaf(v31, wj2.y, o[11]));
    }
}

// ---------------------------------------------------------------------------
// Main kernel: PERSISTENT. 148 CTAs, 8 warps each, tile-strided over 1024
// tiles of 256 rows. One barrier total; zero syncs in the tile loop.
// ---------------------------------------------------------------------------
__global__ void __launch_bounds__(THREADS, 1)
mlp_kernel(const float* __restrict__ x,
           const float* __restrict__ W0,
           const float* __restrict__ b0,
           const float* __restrict__ bh,
           const float* __restrict__ Wout,
           const float* __restrict__ bout,
           float* __restrict__ out) {
    extern __shared__ char smem[];
    const uint32_t sb = smem_u32(smem);
    const int tid  = threadIdx.x;
    const int wid  = tid >> 5;
    const int lane = tid & 31;
    const int q    = lane & 3;

    // ---- prefetch ALL 7 layer images (once per CTA, ever) ----
    #pragma unroll
    for (int l = 0; l < NHID; l++) {
        const char* src = (const char*)&g_wimg[l][0];
        uint32_t dst = sb + SM_WBUF + (uint32_t)l * 32768;
        #pragma unroll
        for (int i = 0; i < 8; i++)
            CP_ASYNC16(dst + (uint32_t)(tid + i * THREADS) * 16,
                       src + (size_t)(tid + i * THREADS) * 16);
        CP_COMMIT();
    }

    // ---- stage f16x2 biases ----
    {
        uint32_t* b2s = (uint32_t*)(smem + SM_BIASH);
        for (int i = tid; i < NHID * 64; i += THREADS)
            b2s[i] = pack_f16(bh[2 * i], bh[2 * i + 1]);
    }

    // per-thread ldmatrix address pieces
    const uint32_t nloc = (uint32_t)((lane & 7) + ((lane >> 4) & 1) * 8);
    const uint32_t jbit = (uint32_t)((lane >> 3) & 1);
    uint32_t swz[8];
    #pragma unroll
    for (int s = 0; s < 8; s++)
        swz[s] = nloc * 256 + ((((uint32_t)(2 * s) + jbit) ^ (nloc & 7)) << 4);

    const uint32_t* b2base = (const uint32_t*)(smem + SM_BIASH);

    // ---- THE ONLY BARRIER in the entire kernel ----
    CP_WAIT(0);
    __syncthreads();

    uint32_t A0a[8][4], A0b[8][4], A1a[8][4], A1b[8][4];

    // ================= persistent tile loop, zero synchronization ==========
    #pragma unroll 1
    for (int tile = blockIdx.x; tile < NTILES; tile += NCTAS) {
        const int rbase = tile * TILE_ROWS + wid * 32 + (lane >> 2);
        const int g0 = rbase, g1 = rbase + 8, g2 = rbase + 16, g3 = rbase + 24;

        // ---- layer 0: [3 -> 128] fp32 FFMA (W0/b0 via L2) -> fp16 A ----
        {
            const float x00 = x[g0 * 3 + 0], x01 = x[g0 * 3 + 1], x02 = x[g0 * 3 + 2];
            const float x10 = x[g1 * 3 + 0], x11 = x[g1 * 3 + 1], x12 = x[g1 * 3 + 2];
            const float x20 = x[g2 * 3 + 0], x21 = x[g2 * 3 + 1], x22 = x[g2 * 3 + 2];
            const float x30 = x[g3 * 3 + 0], x31 = x[g3 * 3 + 1], x32 = x[g3 * 3 + 2];
            #pragma unroll
            for (int s = 0; s < 8; s++) {
                const int c0 = 16 * s + 2 * q;
                #pragma unroll
                for (int h = 0; h < 2; h++) {
                    const int ca = c0 + 8 * h;
                    const float wa0 = W0[ca * 3 + 0], wa1 = W0[ca * 3 + 1], wa2 = W0[ca * 3 + 2];
                    const float wb0 = W0[(ca + 1) * 3 + 0], wb1 = W0[(ca + 1) * 3 + 1], wb2 = W0[(ca + 1) * 3 + 2];
                    const float ba = b0[ca], bb = b0[ca + 1];
                    float v00 = relu(fmaf(x00, wa0, fmaf(x01, wa1, fmaf(x02, wa2, ba))));
                    float v01 = relu(fmaf(x00, wb0, fmaf(x01, wb1, fmaf(x02, wb2, bb))));
                    float v10 = relu(fmaf(x10, wa0, fmaf(x11, wa1, fmaf(x12, wa2, ba))));
                    float v11 = relu(fmaf(x10, wb0, fmaf(x11, wb1, fmaf(x12, wb2, bb))));
                    A0a[s][2 * h + 0] = pack_f16(v00, v01);
                    A0a[s][2 * h + 1] = pack_f16(v10, v11);
                    float v20 = relu(fmaf(x20, wa0, fmaf(x21, wa1, fmaf(x22, wa2, ba))));
                    float v21 = relu(fmaf(x20, wb0, fmaf(x21, wb1, fmaf(x22, wb2, bb))));
                    float v30 = relu(fmaf(x30, wa0, fmaf(x31, wa1, fmaf(x32, wa2, ba))));
                    float v31 = relu(fmaf(x30, wb0, fmaf(x31, wb1, fmaf(x32, wb2, bb))));
                    A0b[s][2 * h + 0] = pack_f16(v20, v21);
                    A0b[s][2 * h + 1] = pack_f16(v30, v31);
                }
            }
        }

        // ---- 6 hidden layers, no syncs ----
        #pragma unroll 1
        for (int it = 0; it < 3; it++) {
            const int l0 = 2 * it;
            hidden_layer(sb + SM_WBUF + (uint32_t)l0 * 32768, swz, q,
                         A0a, A0b, A1a, A1b, b2base + l0 * 64);
            hidden_layer(sb + SM_WBUF + (uint32_t)(l0 + 1) * 32768, swz, q,
                         A1a, A1b, A0a, A0b, b2base + (l0 + 1) * 64);
        }

        // ---- final layer (l=6): MMA + fused [128->3] projection ----
        float o[12];
        #pragma unroll
        for (int i = 0; i < 12; i++) o[i] = 0.f;
        final_layer(sb + SM_WBUF + 6u * 32768, swz, q, A0a, A0b,
                    bh + 6 * 128, Wout, o);

        #pragma unroll
        for (int d = 1; d <= 2; d <<= 1) {
            #pragma unroll
            for (int i = 0; i < 12; i++)
                o[i] += __shfl_xor_sync(0xFFFFFFFF, o[i], d);
        }
        if (q == 0) {
            const float bo0 = bout[0], bo1 = bout[1], bo2 = bout[2];
            out[g0 * 3 + 0] = o[0] + bo0;
            out[g0 * 3 + 1] = o[1] + bo1;
            out[g0 * 3 + 2] = o[2] + bo2;
            out[g1 * 3 + 0] = o[3] + bo0;
            out[g1 * 3 + 1] = o[4] + bo1;
            out[g1 * 3 + 2] = o[5] + bo2;
            out[g2 * 3 + 0] = o[6] + bo0;
            out[g2 * 3 + 1] = o[7] + bo1;
            out[g2 * 3 + 2] = o[8] + bo2;
            out[g3 * 3 + 0] = o[9] + bo0;
            out[g3 * 3 + 1] = o[10] + bo1;
            out[g3 * 3 + 2] = o[11] + bo2;
        }
    }
}

// ---------------------------------------------------------------------------
// kernel_launch
// ---------------------------------------------------------------------------
extern "C" void kernel_launch(void* const* d_in, const int* in_sizes, int n_in,
                              void* d_out, int out_size) {
    const float* x    = (const float*)d_in[0];   // [262144,3]
    const float* W0   = (const float*)d_in[1];   // [128,3]
    const float* b0   = (const float*)d_in[2];   // [128]
    const float* Wh   = (const float*)d_in[3];   // [7,128,128]
    const float* bh   = (const float*)d_in[4];   // [7,128]
    const float* Wout = (const float*)d_in[5];   // [3,128]
    const float* bout = (const float*)d_in[6];   // [3]
    float* out = (float*)d_out;                  // [262144,3]

    static bool attr_set = false;
    if (!attr_set) {
        cudaFuncSetAttribute(mlp_kernel,
                             cudaFuncAttributeMaxDynamicSharedMemorySize, SMEM_SZ);
        attr_set = true;
    }

    prep_weights_kernel<<<(NHID * 128 * 128 + 255) / 256, 256>>>(Wh);
    mlp_kernel<<<NCTAS, THREADS, SMEM_SZ>>>(x, W0, b0, bh, Wout, bout, out);
}

// round 13
// speedup vs baseline: 1.0291x; 1.0088x over previous
#include <cuda_runtime.h>
#include <cuda_fp16.h>
#include <cstdint>

// ============================================================================
// NSFPRawMLP: x[262144,3] -> 128 -> (7x 128x128 + ReLU) -> 3
// R13: R12 (persistent, 148 CTAs, all weights SMEM-resident, zero-sync loop)
// + DELIBERATE WARP ANTI-PHASING: warps 4-7 delay ~2600 cyc once at start, so
// the two warps sharing each SMSP stay ~half a layer out of phase forever --
// one warp's epilogue overlaps the other's MMA stream.
// ============================================================================

#define NROWS    262144
#define NHID     7
#define TILE_ROWS 256
#define NTILES   (NROWS / TILE_ROWS)     // 1024 tiles
#define NCTAS    148                     // persistent: one per SM
#define THREADS  256                     // 8 warps, 32 rows/warp
#define SKEW_CYCLES 2600ull

// Weight images: [layer][32768 B] fp16.
// byte = n*256 + ((chunk ^ (n&7))<<4) + (k&7)*2, chunk = k>>3  (XOR swizzle)
static __device__ __align__(128) unsigned char g_wimg[NHID][32768];

// ---------------------------------------------------------------------------
// SMEM layout: 7 weight buffers + f16x2 biases. W0/b0/Wout/bout via gmem/L1.
// ---------------------------------------------------------------------------
#define SM_WBUF    0                     // 7 x 32768 = 229376
#define SM_BIASH   229376                // 7*64 half2 = 1792
#define SMEM_SZ    231168                // 225.75 KB

// ---------------------------------------------------------------------------
// PTX helpers (base-target, sm_80+)
// ---------------------------------------------------------------------------
__device__ __forceinline__ uint32_t smem_u32(const void* p) {
    uint32_t a;
    asm("{ .reg .u64 t; cvta.to.shared.u64 t, %1; cvt.u32.u64 %0, t; }"
        : "=r"(a) : "l"(p));
    return a;
}

#define CP_ASYNC16(dst_u32, src_ptr) \
    asm volatile("cp.async.cg.shared.global [%0], [%1], 16;" \
                 :: "r"(dst_u32), "l"(src_ptr) : "memory")
#define CP_COMMIT() asm volatile("cp.async.commit_group;" ::: "memory")
#define CP_WAIT(n)  asm volatile("cp.async.wait_group %0;" :: "n"(n) : "memory")

#define LDSM4(r0, r1, r2, r3, addr) \
    asm volatile("ldmatrix.sync.aligned.m8n8.x4.shared.b16 {%0,%1,%2,%3}, [%4];" \
                 : "=r"(r0), "=r"(r1), "=r"(r2), "=r"(r3) : "r"(addr))

#define MMA16816(C, A, b0_, b1_) \
    asm volatile("mma.sync.aligned.m16n8k16.row.col.f32.f16.f16.f32 " \
                 "{%0,%1,%2,%3},{%4,%5,%6,%7},{%8,%9},{%0,%1,%2,%3};" \
                 : "+f"((C)[0]), "+f"((C)[1]), "+f"((C)[2]), "+f"((C)[3]) \
                 : "r"((A)[0]), "r"((A)[1]), "r"((A)[2]), "r"((A)[3]), \
                   "r"(b0_), "r"(b1_))

// pack two fp32 -> fp16x2 (round-to-nearest)
__device__ __forceinline__ uint32_t pack_f16(float v0, float v1) {
    uint32_t r;
    asm("cvt.rn.f16x2.f32 %0, %1, %2;" : "=r"(r) : "f"(v1), "f"(v0));
    return r;
}

__device__ __forceinline__ float relu(float v) { return fmaxf(v, 0.0f); }

// f16x2 epilogue op: pack(c0,c1) + bias2 (f16), relu via hmax2
__device__ __forceinline__ uint32_t epi_op(float c0, float c1, uint32_t b2) {
    uint32_t v = pack_f16(c0, c1);
    __half2 hv = __hadd2(*reinterpret_cast<__half2*>(&v),
                         *reinterpret_cast<const __half2*>(&b2));
    const __half2 z = __floats2half2_rn(0.f, 0.f);
    hv = __hmax2(hv, z);
    return *reinterpret_cast<uint32_t*>(&hv);
}

__device__ __forceinline__ void epi_sg(uint32_t (&Aout)[4],
                                       const float (&C0)[4], const float (&C1)[4],
                                       uint32_t b20, uint32_t b21) {
    Aout[0] = epi_op(C0[0], C0[1], b20);
    Aout[1] = epi_op(C0[2], C0[3], b20);
    Aout[2] = epi_op(C1[0], C1[1], b21);
    Aout[3] = epi_op(C1[2], C1[3], b21);
}

// ---------------------------------------------------------------------------
// Prep kernel: Wh fp32 -> fp16 swizzled image.
// ---------------------------------------------------------------------------
__global__ void prep_weights_kernel(const float* __restrict__ Wh) {
    int idx = blockIdx.x * blockDim.x + threadIdx.x;
    if (idx >= NHID * 128 * 128) return;
    int l = idx >> 14;
    int n = (idx >> 7) & 127;
    int k = idx & 127;
    __half w = __float2half_rn(Wh[idx]);
    uint32_t chunk = (uint32_t)k >> 3;
    uint32_t off = (uint32_t)n * 256 + ((chunk ^ ((uint32_t)n & 7)) << 4)
                 + ((uint32_t)k & 7) * 2;
    *(__half*)&g_wimg[l][off] = w;
}

// ---------------------------------------------------------------------------
// One hidden layer: pp-outer k-loop, per-block epilogue overlapped. No syncs.
// ---------------------------------------------------------------------------
__device__ __forceinline__ void hidden_layer(
    uint32_t wb, const uint32_t (&swz)[8], int q,
    uint32_t (&Aia)[8][4], uint32_t (&Aib)[8][4],
    uint32_t (&Aoa)[8][4], uint32_t (&Aob)[8][4],
    const uint32_t* __restrict__ b2) {
    float Ca[16][4], Cb[16][4];
    uint32_t h[2][8];
    LDSM4(h[0][0], h[0][1], h[0][2], h[0][3], wb + swz[0]);
    LDSM4(h[0][4], h[0][5], h[0][6], h[0][7], wb + swz[0] + 4096);
    #pragma unroll
    for (int grp = 0; grp < 32; grp++) {
        const int cur = grp & 1, nxt = cur ^ 1;
        const int pp = grp >> 3, s = grp & 7;
        if (grp + 1 < 32) {
            const int pp1 = (grp + 1) >> 3, s1 = (grp + 1) & 7;
            const uint32_t a0 = wb + swz[s1] + (uint32_t)(2 * pp1) * 4096;
            LDSM4(h[nxt][0], h[nxt][1], h[nxt][2], h[nxt][3], a0);
            LDSM4(h[nxt][4], h[nxt][5], h[nxt][6], h[nxt][7], a0 + 4096);
        }
        if (s == 0) {
            #pragma unroll
            for (int j = 0; j < 4; j++) {
                Ca[4 * pp + j][0] = 0.f; Ca[4 * pp + j][1] = 0.f;
                Ca[4 * pp + j][2] = 0.f; Ca[4 * pp + j][3] = 0.f;
                Cb[4 * pp + j][0] = 0.f; Cb[4 * pp + j][1] = 0.f;
                Cb[4 * pp + j][2] = 0.f; Cb[4 * pp + j][3] = 0.f;
            }
        }
        MMA16816(Ca[4 * pp + 0], Aia[s], h[cur][0], h[cur][1]);
        MMA16816(Cb[4 * pp + 0], Aib[s], h[cur][0], h[cur][1]);
        MMA16816(Ca[4 * pp + 1], Aia[s], h[cur][2], h[cur][3]);
        MMA16816(Cb[4 * pp + 1], Aib[s], h[cur][2], h[cur][3]);
        MMA16816(Ca[4 * pp + 2], Aia[s], h[cur][4], h[cur][5]);
        MMA16816(Cb[4 * pp + 2], Aib[s], h[cur][4], h[cur][5]);
        MMA16816(Ca[4 * pp + 3], Aia[s], h[cur][6], h[cur][7]);
        MMA16816(Cb[4 * pp + 3], Aib[s], h[cur][6], h[cur][7]);
        if (s == 1 && pp > 0) {
            const int p0 = pp - 1;
            #pragma unroll
            for (int e = 0; e < 2; e++) {
                const int sg = 2 * p0 + e;
                const uint32_t b20 = b2[8 * sg + q];
                const uint32_t b21 = b2[8 * sg + 4 + q];
                epi_sg(Aoa[sg], Ca[2 * sg], Ca[2 * sg + 1], b20, b21);
                epi_sg(Aob[sg], Cb[2 * sg], Cb[2 * sg + 1], b20, b21);
            }
        }
    }
    #pragma unroll
    for (int e = 0; e < 2; e++) {
        const int sg = 6 + e;
        const uint32_t b20 = b2[8 * sg + q];
        const uint32_t b21 = b2[8 * sg + 4 + q];
        epi_sg(Aoa[sg], Ca[2 * sg], Ca[2 * sg + 1], b20, b21);
        epi_sg(Aob[sg], Cb[2 * sg], Cb[2 * sg + 1], b20, b21);
    }
}

// ---------------------------------------------------------------------------
// Final layer: per-block fp32 bias+relu+[128->3] projection (params via L1).
// ---------------------------------------------------------------------------
__device__ __forceinline__ void final_layer(
    uint32_t wb, const uint32_t (&swz)[8], int q,
    uint32_t (&Aia)[8][4], uint32_t (&Aib)[8][4],
    const float* __restrict__ bl, const float* __restrict__ wout,
    float (&o)[12]) {
    float Ca[16][4], Cb[16][4];
    uint32_t h[2][8];
    LDSM4(h[0][0], h[0][1], h[0][2], h[0][3], wb + swz[0]);
    LDSM4(h[0][4], h[0][5], h[0][6], h[0][7], wb + swz[0] + 4096);
    #pragma unroll
    for (int grp = 0; grp < 32; grp++) {
        const int cur = grp & 1, nxt = cur ^ 1;
        const int pp = grp >> 3, s = grp & 7;
        if (grp + 1 < 32) {
            const int pp1 = (grp + 1) >> 3, s1 = (grp + 1) & 7;
            const uint32_t a0 = wb + swz[s1] + (uint32_t)(2 * pp1) * 4096;
            LDSM4(h[nxt][0], h[nxt][1], h[nxt][2], h[nxt][3], a0);
            LDSM4(h[nxt][4], h[nxt][5], h[nxt][6], h[nxt][7], a0 + 4096);
        }
        if (s == 0) {
            #pragma unroll
            for (int j = 0; j < 4; j++) {
                Ca[4 * pp + j][0] = 0.f; Ca[4 * pp + j][1] = 0.f;
                Ca[4 * pp + j][2] = 0.f; Ca[4 * pp + j][3] = 0.f;
                Cb[4 * pp + j][0] = 0.f; Cb[4 * pp + j][1] = 0.f;
                Cb[4 * pp + j][2] = 0.f; Cb[4 * pp + j][3] = 0.f;
            }
        }
        MMA16816(Ca[4 * pp + 0], Aia[s], h[cur][0], h[cur][1]);
        MMA16816(Cb[4 * pp + 0], Aib[s], h[cur][0], h[cur][1]);
        MMA16816(Ca[4 * pp + 1], Aia[s], h[cur][2], h[cur][3]);
        MMA16816(Cb[4 * pp + 1], Aib[s], h[cur][2], h[cur][3]);
        MMA16816(Ca[4 * pp + 2], Aia[s], h[cur][4], h[cur][5]);
        MMA16816(Cb[4 * pp + 2], Aib[s], h[cur][4], h[cur][5]);
        MMA16816(Ca[4 * pp + 3], Aia[s], h[cur][6], h[cur][7]);
        MMA16816(Cb[4 * pp + 3], Aib[s], h[cur][6], h[cur][7]);
        if (s == 1 && pp > 0) {
            const int p0 = pp - 1;
            #pragma unroll
            for (int g = 4 * p0; g < 4 * p0 + 4; g++) {
                const int c = 8 * g + 2 * q;
                const float2 bb  = *(const float2*)&bl[c];
                const float2 wj0 = *(const float2*)&wout[0 * 128 + c];
                const float2 wj1 = *(const float2*)&wout[1 * 128 + c];
                const float2 wj2 = *(const float2*)&wout[2 * 128 + c];
                float v00 = relu(Ca[g][0] + bb.x), v01 = relu(Ca[g][1] + bb.y);
                float v10 = relu(Ca[g][2] + bb.x), v11 = relu(Ca[g][3] + bb.y);
                float v20 = relu(Cb[g][0] + bb.x), v21 = relu(Cb[g][1] + bb.y);
                float v30 = relu(Cb[g][2] + bb.x), v31 = relu(Cb[g][3] + bb.y);
                o[0]  = fmaf(v00, wj0.x, fmaf(v01, wj0.y, o[0]));
                o[1]  = fmaf(v00, wj1.x, fmaf(v01, wj1.y, o[1]));
                o[2]  = fmaf(v00, wj2.x, fmaf(v01, wj2.y, o[2]));
                o[3]  = fmaf(v10, wj0.x, fmaf(v11, wj0.y, o[3]));
                o[4]  = fmaf(v10, wj1.x, fmaf(v11, wj1.y, o[4]));
                o[5]  = fmaf(v10, wj2.x, fmaf(v11, wj2.y, o[5]));
                o[6]  = fmaf(v20, wj0.x, fmaf(v21, wj0.y, o[6]));
                o[7]  = fmaf(v20, wj1.x, fmaf(v21, wj1.y, o[7]));
                o[8]  = fmaf(v20, wj2.x, fmaf(v21, wj2.y, o[8]));
                o[9]  = fmaf(v30, wj0.x, fmaf(v31, wj0.y, o[9]));
                o[10] = fmaf(v30, wj1.x, fmaf(v31, wj1.y, o[10]));
                o[11] = fmaf(v30, wj2.x, fmaf(v31, wj2.y, o[11]));
            }
        }
    }
    #pragma unroll
    for (int g = 12; g < 16; g++) {
        const int c = 8 * g + 2 * q;
        const float2 bb  = *(const float2*)&bl[c];
        const float2 wj0 = *(const float2*)&wout[0 * 128 + c];
        const float2 wj1 = *(const float2*)&wout[1 * 128 + c];
        const float2 wj2 = *(const float2*)&wout[2 * 128 + c];
        float v00 = relu(Ca[g][0] + bb.x), v01 = relu(Ca[g][1] + bb.y);
        float v10 = relu(Ca[g][2] + bb.x), v11 = relu(Ca[g][3] + bb.y);
        float v20 = relu(Cb[g][0] + bb.x), v21 = relu(Cb[g][1] + bb.y);
        float v30 = relu(Cb[g][2] + bb.x), v31 = relu(Cb[g][3] + bb.y);
        o[0]  = fmaf(v00, wj0.x, fmaf(v01, wj0.y, o[0]));
        o[1]  = fmaf(v00, wj1.x, fmaf(v01, wj1.y, o[1]));
        o[2]  = fmaf(v00, wj2.x, fmaf(v01, wj2.y, o[2]));
        o[3]  = fmaf(v10, wj0.x, fmaf(v11, wj0.y, o[3]));
        o[4]  = fmaf(v10, wj1.x, fmaf(v11, wj1.y, o[4]));
        o[5]  = fmaf(v10, wj2.x, fmaf(v11, wj2.y, o[5]));
        o[6]  = fmaf(v20, wj0.x, fmaf(v21, wj0.y, o[6]));
        o[7]  = fmaf(v20, wj1.x, fmaf(v21, wj1.y, o[7]));
        o[8]  = fmaf(v20, wj2.x, fmaf(v21, wj2.y, o[8]));
        o[9]  = fmaf(v30, wj0.x, fmaf(v31, wj0.y, o[9]));
        o[10] = fmaf(v30, wj1.x, fmaf(v31, wj1.y, o[10]));
        o[11] = fmaf(v30, wj2.x, fmaf(v31, wj2.y, o[11]));
    }
}

// ---------------------------------------------------------------------------
// Main kernel: PERSISTENT. 148 CTAs, 8 warps each, anti-phased warp pairs.
// ---------------------------------------------------------------------------
__global__ void __launch_bounds__(THREADS, 1)
mlp_kernel(const float* __restrict__ x,
           const float* __restrict__ W0,
           const float* __restrict__ b0,
           const float* __restrict__ bh,
           const float* __restrict__ Wout,
           const float* __restrict__ bout,
           float* __restrict__ out) {
    extern __shared__ char smem[];
    const uint32_t sb = smem_u32(smem);
    const int tid  = threadIdx.x;
    const int wid  = tid >> 5;
    const int lane = tid & 31;
    const int q    = lane & 3;

    // ---- prefetch ALL 7 layer images (once per CTA, ever) ----
    #pragma unroll
    for (int l = 0; l < NHID; l++) {
        const char* src = (const char*)&g_wimg[l][0];
        uint32_t dst = sb + SM_WBUF + (uint32_t)l * 32768;
        #pragma unroll
        for (int i = 0; i < 8; i++)
            CP_ASYNC16(dst + (uint32_t)(tid + i * THREADS) * 16,
                       src + (size_t)(tid + i * THREADS) * 16);
        CP_COMMIT();
    }

    // ---- stage f16x2 biases ----
    {
        uint32_t* b2s = (uint32_t*)(smem + SM_BIASH);
        for (int i = tid; i < NHID * 64; i += THREADS)
            b2s[i] = pack_f16(bh[2 * i], bh[2 * i + 1]);
    }

    // per-thread ldmatrix address pieces
    const uint32_t nloc = (uint32_t)((lane & 7) + ((lane >> 4) & 1) * 8);
    const uint32_t jbit = (uint32_t)((lane >> 3) & 1);
    uint32_t swz[8];
    #pragma unroll
    for (int s = 0; s < 8; s++)
        swz[s] = nloc * 256 + ((((uint32_t)(2 * s) + jbit) ^ (nloc & 7)) << 4);

    const uint32_t* b2base = (const uint32_t*)(smem + SM_BIASH);

    // ---- THE ONLY BARRIER in the entire kernel ----
    CP_WAIT(0);
    __syncthreads();

    // ---- ANTI-PHASE: second warp of each SMSP pair delays ~half a layer.
    // With identical streams and no further barriers, the skew persists
    // for the whole kernel: warp-lo epilogue overlaps warp-hi MMAs.
    if (wid >= 4) {
        unsigned long long t0 = clock64();
        while (clock64() - t0 < SKEW_CYCLES) { }
    }

    uint32_t A0a[8][4], A0b[8][4], A1a[8][4], A1b[8][4];

    // ================= persistent tile loop, zero synchronization ==========
    #pragma unroll 1
    for (int tile = blockIdx.x; tile < NTILES; tile += NCTAS) {
        const int rbase = tile * TILE_ROWS + wid * 32 + (lane >> 2);
        const int g0 = rbase, g1 = rbase + 8, g2 = rbase + 16, g3 = rbase + 24;

        // ---- layer 0: [3 -> 128] fp32 FFMA (W0/b0 via L1) -> fp16 A ----
        {
            const float x00 = x[g0 * 3 + 0], x01 = x[g0 * 3 + 1], x02 = x[g0 * 3 + 2];
            const float x10 = x[g1 * 3 + 0], x11 = x[g1 * 3 + 1], x12 = x[g1 * 3 + 2];
            const float x20 = x[g2 * 3 + 0], x21 = x[g2 * 3 + 1], x22 = x[g2 * 3 + 2];
            const float x30 = x[g3 * 3 + 0], x31 = x[g3 * 3 + 1], x32 = x[g3 * 3 + 2];
            #pragma unroll
            for (int s = 0; s < 8; s++) {
                const int c0 = 16 * s + 2 * q;
                #pragma unroll
                for (int h = 0; h < 2; h++) {
                    const int ca = c0 + 8 * h;
                    const float wa0 = W0[ca * 3 + 0], wa1 = W0[ca * 3 + 1], wa2 = W0[ca * 3 + 2];
                    const float wb0 = W0[(ca + 1) * 3 + 0], wb1 = W0[(ca + 1) * 3 + 1], wb2 = W0[(ca + 1) * 3 + 2];
                    const float ba = b0[ca], bb = b0[ca + 1];
                    float v00 = relu(fmaf(x00, wa0, fmaf(x01, wa1, fmaf(x02, wa2, ba))));
                    float v01 = relu(fmaf(x00, wb0, fmaf(x01, wb1, fmaf(x02, wb2, bb))));
                    float v10 = relu(fmaf(x10, wa0, fmaf(x11, wa1, fmaf(x12, wa2, ba))));
                    float v11 = relu(fmaf(x10, wb0, fmaf(x11, wb1, fmaf(x12, wb2, bb))));
                    A0a[s][2 * h + 0] = pack_f16(v00, v01);
                    A0a[s][2 * h + 1] = pack_f16(v10, v11);
                    float v20 = relu(fmaf(x20, wa0, fmaf(x21, wa1, fmaf(x22, wa2, ba))));
                    float v21 = relu(fmaf(x20, wb0, fmaf(x21, wb1, fmaf(x22, wb2, bb))));
                    float v30 = relu(fmaf(x30, wa0, fmaf(x31, wa1, fmaf(x32, wa2, ba))));
                    float v31 = relu(fmaf(x30, wb0, fmaf(x31, wb1, fmaf(x32, wb2, bb))));
                    A0b[s][2 * h + 0] = pack_f16(v20, v21);
                    A0b[s][2 * h + 1] = pack_f16(v30, v31);
                }
            }
        }

        // ---- 6 hidden layers, no syncs ----
        #pragma unroll 1
        for (int it = 0; it < 3; it++) {
            const int l0 = 2 * it;
            hidden_layer(sb + SM_WBUF + (uint32_t)l0 * 32768, swz, q,
                         A0a, A0b, A1a, A1b, b2base + l0 * 64);
            hidden_layer(sb + SM_WBUF + (uint32_t)(l0 + 1) * 32768, swz, q,
                         A1a, A1b, A0a, A0b, b2base + (l0 + 1) * 64);
        }

        // ---- final layer (l=6): MMA + fused [128->3] projection ----
        float o[12];
        #pragma unroll
        for (int i = 0; i < 12; i++) o[i] = 0.f;
        final_layer(sb + SM_WBUF + 6u * 32768, swz, q, A0a, A0b,
                    bh + 6 * 128, Wout, o);

        #pragma unroll
        for (int d = 1; d <= 2; d <<= 1) {
            #pragma unroll
            for (int i = 0; i < 12; i++)
                o[i] += __shfl_xor_sync(0xFFFFFFFF, o[i], d);
        }
        if (q == 0) {
            const float bo0 = bout[0], bo1 = bout[1], bo2 = bout[2];
            out[g0 * 3 + 0] = o[0] + bo0;
            out[g0 * 3 + 1] = o[1] + bo1;
            out[g0 * 3 + 2] = o[2] + bo2;
            out[g1 * 3 + 0] = o[3] + bo0;
            out[g1 * 3 + 1] = o[4] + bo1;
            out[g1 * 3 + 2] = o[5] + bo2;
            out[g2 * 3 + 0] = o[6] + bo0;
            out[g2 * 3 + 1] = o[7] + bo1;
            out[g2 * 3 + 2] = o[8] + bo2;
            out[g3 * 3 + 0] = o[9] + bo0;
            out[g3 * 3 + 1] = o[10] + bo1;
            out[g3 * 3 + 2] = o[11] + bo2;
        }
    }
}

// ---------------------------------------------------------------------------
// kernel_launch
// ---------------------------------------------------------------------------
extern "C" void kernel_launch(void* const* d_in, const int* in_sizes, int n_in,
                              void* d_out, int out_size) {
    const float* x    = (const float*)d_in[0];   // [262144,3]
    const float* W0   = (const float*)d_in[1];   // [128,3]
    const float* b0   = (const float*)d_in[2];   // [128]
    const float* Wh   = (const float*)d_in[3];   // [7,128,128]
    const float* bh   = (const float*)d_in[4];   // [7,128]
    const float* Wout = (const float*)d_in[5];   // [3,128]
    const float* bout = (const float*)d_in[6];   // [3]
    float* out = (float*)d_out;                  // [262144,3]

    static bool attr_set = false;
    if (!attr_set) {
        cudaFuncSetAttribute(mlp_kernel,
                             cudaFuncAttributeMaxDynamicSharedMemorySize, SMEM_SZ);
        attr_set = true;
    }

    prep_weights_kernel<<<(NHID * 128 * 128 + 255) / 256, 256>>>(Wh);
    mlp_kernel<<<NCTAS, THREADS, SMEM_SZ>>>(x, W0, b0, bh, Wout, bout, out);
}